// round 3
// baseline (speedup 1.0000x reference)
#include <cuda_runtime.h>

#define NUM_EMB 41025
#define BATCH   16384
#define BAG     30
#define H1      256
#define H2      32
#define H3      32
#define R       4          // batch rows per block
#define THREADS 256

__device__ int g_idx_is64;

// Detect whether index arrays are int64 (JAX x64 mode) or int32.
// For little-endian int64 with values < 2^31, every odd 32-bit word is 0.
__global__ void detect_idx_dtype(const unsigned* wi) {
    if (threadIdx.x == 0 && blockIdx.x == 0) {
        int is64 = 1;
        #pragma unroll 1
        for (int k = 0; k < 32; ++k) {
            if (wi[2 * k + 1] != 0u) { is64 = 0; break; }
        }
        g_idx_is64 = is64;
    }
}

__global__ __launch_bounds__(THREADS) void nnue_kernel(
    const void* __restrict__ wi_raw, const void* __restrict__ bi_raw,
    const float* __restrict__ ftw, const float* __restrict__ ftb,
    const float* __restrict__ w1,  const float* __restrict__ b1,
    const float* __restrict__ w2,  const float* __restrict__ b2,
    const float* __restrict__ w3,  const float* __restrict__ b3,
    float* __restrict__ out)
{
    __shared__ int   s_idx[2][R][BAG];
    __shared__ float xs[R][2 * H1];          // 8 KB: concat(relu(w), relu(b)) per row
    __shared__ float h1s[R][H2];
    __shared__ float h2s[R][H3];
    __shared__ float s_w2[H2 * 33];          // padded stride 33 -> conflict-free
    __shared__ float s_b1[H2], s_b2[H2], s_w3[H3];
    __shared__ float s_b3;

    const int tid  = threadIdx.x;
    const int row0 = blockIdx.x * R;
    const int is64 = g_idx_is64;

    // ---- load indices for this block's R rows (both colors) ----
    if (tid < 2 * R * BAG) {                 // 240 threads
        int h   = tid / (R * BAG);
        int rem = tid % (R * BAG);
        int r   = rem / BAG, i = rem % BAG;
        const void* src = h ? bi_raw : wi_raw;
        long long pos = (long long)(row0 + r) * BAG + i;
        int idx;
        if (is64) idx = (int)((const long long*)src)[pos];
        else      idx = ((const int*)src)[pos];
        s_idx[h][r][i] = idx;
    }
    // ---- stage small weights into shared ----
    for (int j = tid; j < H2 * H2; j += THREADS) {
        int jr = j / H2, jc = j % H2;
        s_w2[jr * 33 + jc] = w2[j];
    }
    if      (tid < H2)            s_b1[tid] = b1[tid];
    else if (tid < 2 * H2)        s_b2[tid - H2] = b2[tid - H2];
    else if (tid < 2 * H2 + H3)   s_w3[tid - 2 * H2] = w3[tid - 2 * H2];
    else if (tid == 2 * H2 + H3)  s_b3 = b3[0];
    __syncthreads();

    // ---- phase 1: embedding-bag gathers (L2-bound hot loop) ----
    {
        const int h = tid >> 7;              // 0 = white, 1 = black
        const int l = tid & 127;             // float2 column within the 256-wide row
        const float2* table = (const float2*)(h ? ftb : ftw);
        #pragma unroll 1
        for (int r = 0; r < R; ++r) {
            float accx = 0.f, accy = 0.f;
            #pragma unroll
            for (int i = 0; i < BAG; ++i) {
                int idx = s_idx[h][r][i];
                float2 v = __ldcg(table + (size_t)idx * (H1 / 2) + l);
                accx += v.x; accy += v.y;
            }
            float2 acc = make_float2(fmaxf(accx, 0.f), fmaxf(accy, 0.f));
            ((float2*)xs[r])[h * 128 + l] = acc;
        }
    }
    __syncthreads();

    // ---- phase 2: fc1 (32 x 512), W1 loaded into registers once per block ----
    {
        const int warp = tid >> 5, lane = tid & 31;
        #pragma unroll
        for (int jj = 0; jj < 4; ++jj) {
            int j = warp * 4 + jj;           // 8 warps x 4 = 32 outputs
            float w1r[16];
            #pragma unroll
            for (int m = 0; m < 16; ++m)
                w1r[m] = w1[j * 512 + lane + 32 * m];   // coalesced, L1-resident
            #pragma unroll
            for (int r = 0; r < R; ++r) {
                float s = 0.f;
                #pragma unroll
                for (int m = 0; m < 16; ++m)
                    s += w1r[m] * xs[r][lane + 32 * m];
                #pragma unroll
                for (int o = 16; o > 0; o >>= 1)
                    s += __shfl_xor_sync(0xffffffffu, s, o);
                if (lane == 0) h1s[r][j] = fmaxf(s + s_b1[j], 0.f);
            }
        }
    }
    __syncthreads();

    // ---- phase 3: fc2 (32 x 32) ----
    if (tid < R * H2) {
        int r = tid >> 5, j = tid & 31;
        float s = s_b2[j];
        #pragma unroll
        for (int k = 0; k < H2; ++k)
            s += h1s[r][k] * s_w2[j * 33 + k];
        h2s[r][j] = fmaxf(s, 0.f);
    }
    __syncthreads();

    // ---- phase 4: fc3 (1 x 32) ----
    if (tid < R) {
        float s = s_b3;
        #pragma unroll
        for (int k = 0; k < H3; ++k)
            s += h2s[tid][k] * s_w3[k];
        out[row0 + tid] = s;
    }
}

extern "C" void kernel_launch(void* const* d_in, const int* in_sizes, int n_in,
                              void* d_out, int out_size) {
    // metadata order:
    // 0 white_indices, 1 white_offsets (unused), 2 black_indices,
    // 3 black_offsets (unused), 4 ft_white, 5 ft_black,
    // 6 fc1_w, 7 fc1_b, 8 fc2_w, 9 fc2_b, 10 fc3_w, 11 fc3_b
    const void*  wi  = d_in[0];
    const void*  bi  = d_in[2];
    const float* ftw = (const float*)d_in[4];
    const float* ftb = (const float*)d_in[5];
    const float* w1  = (const float*)d_in[6];
    const float* b1  = (const float*)d_in[7];
    const float* w2  = (const float*)d_in[8];
    const float* b2  = (const float*)d_in[9];
    const float* w3  = (const float*)d_in[10];
    const float* b3  = (const float*)d_in[11];

    detect_idx_dtype<<<1, 32>>>((const unsigned*)wi);
    nnue_kernel<<<BATCH / R, THREADS>>>(wi, bi, ftw, ftb,
                                        w1, b1, w2, b2, w3, b3,
                                        (float*)d_out);
}

// round 4
// speedup vs baseline: 1.1247x; 1.1247x over previous
#include <cuda_runtime.h>

#define NUM_EMB 41025
#define BATCH   16384
#define BAG     30
#define H1      256
#define H2      32
#define H3      32
#define R       8          // batch rows per block
#define THREADS 256

__global__ __launch_bounds__(THREADS, 4) void nnue_kernel(
    const void* __restrict__ wi_raw, const void* __restrict__ bi_raw,
    const float* __restrict__ ftw, const float* __restrict__ ftb,
    const float* __restrict__ w1,  const float* __restrict__ b1,
    const float* __restrict__ w2,  const float* __restrict__ b2,
    const float* __restrict__ w3,  const float* __restrict__ b3,
    float* __restrict__ out)
{
    __shared__ int   s_idx[2][R][BAG];
    __shared__ float xs[R][2 * H1];          // 16 KB: concat(relu(w), relu(b)) per row
    __shared__ float h1s[R][H2];
    __shared__ float h2s[R][H3];
    __shared__ float s_w2[H2 * 33];          // padded stride 33 -> conflict-free
    __shared__ float s_b1[H2], s_b2[H2], s_w3[H3];
    __shared__ float s_b3;
    __shared__ int   s_is64;

    const int tid  = threadIdx.x;
    const int row0 = blockIdx.x * R;

    // ---- inline int32-vs-int64 index dtype detection (64B, L2-cached) ----
    // int64 indices < 2^31 have all odd 32-bit words zero. For int32, the odd
    // words are random indices in [0, 41025); 16 simultaneous zeros ~ impossible.
    if (tid < 16) {
        unsigned v = ((const unsigned*)wi_raw)[2 * tid + 1];
        unsigned nz = __ballot_sync(0xffffu, v != 0u);
        if (tid == 0) s_is64 = (nz == 0u);
    }
    __syncthreads();
    const int is64 = s_is64;

    // ---- load indices for this block's R rows (both colors) ----
    for (int t = tid; t < 2 * R * BAG; t += THREADS) {   // 480 indices
        int h   = t / (R * BAG);
        int rem = t % (R * BAG);
        int r   = rem / BAG, i = rem % BAG;
        const void* src = h ? bi_raw : wi_raw;
        long long pos = (long long)(row0 + r) * BAG + i;
        int idx;
        if (is64) idx = (int)((const long long*)src)[pos];
        else      idx = ((const int*)src)[pos];
        s_idx[h][r][i] = idx;
    }
    // ---- stage small weights into shared ----
    for (int j = tid; j < H2 * H2; j += THREADS) {
        int jr = j / H2, jc = j % H2;
        s_w2[jr * 33 + jc] = w2[j];
    }
    if      (tid < H2)            s_b1[tid] = b1[tid];
    else if (tid < 2 * H2)        s_b2[tid - H2] = b2[tid - H2];
    else if (tid < 2 * H2 + H3)   s_w3[tid - 2 * H2] = w3[tid - 2 * H2];
    else if (tid == 2 * H2 + H3)  s_b3 = b3[0];
    __syncthreads();

    // ---- phase 1: embedding-bag gathers (latency-bound hot loop) ----
    // float4 lanes: 64 threads cover one 256-float row; the 128 threads of a
    // color process 2 batch rows concurrently (sub), halving load-instr count.
    {
        const int h   = tid >> 7;            // 0 = white, 1 = black
        const int sub = (tid >> 6) & 1;      // which of 2 concurrent rows
        const int l   = tid & 63;            // float4 column within the row
        const float4* table = (const float4*)(h ? ftb : ftw);
        #pragma unroll 1
        for (int rr = 0; rr < R / 2; ++rr) {
            const int r = rr * 2 + sub;
            float ax = 0.f, ay = 0.f, az = 0.f, aw = 0.f;
            #pragma unroll
            for (int i = 0; i < BAG; ++i) {
                int idx = s_idx[h][r][i];
                float4 v = __ldcg(table + (size_t)idx * (H1 / 4) + l);
                ax += v.x; ay += v.y; az += v.z; aw += v.w;
            }
            float4 acc = make_float4(fmaxf(ax, 0.f), fmaxf(ay, 0.f),
                                     fmaxf(az, 0.f), fmaxf(aw, 0.f));
            ((float4*)xs[r])[h * (H1 / 4) + l] = acc;
        }
    }
    __syncthreads();

    // ---- phase 2: fc1 (32 x 512), W1 in registers, reused across R rows ----
    {
        const int warp = tid >> 5, lane = tid & 31;
        #pragma unroll 1
        for (int jj = 0; jj < 4; ++jj) {
            int j = warp * 4 + jj;           // 8 warps x 4 = 32 outputs
            float w1r[16];
            #pragma unroll
            for (int m = 0; m < 16; ++m)
                w1r[m] = w1[j * 512 + lane + 32 * m];   // coalesced, L1-hot
            #pragma unroll
            for (int r = 0; r < R; ++r) {
                float s = 0.f;
                #pragma unroll
                for (int m = 0; m < 16; ++m)
                    s += w1r[m] * xs[r][lane + 32 * m];
                #pragma unroll
                for (int o = 16; o > 0; o >>= 1)
                    s += __shfl_xor_sync(0xffffffffu, s, o);
                if (lane == 0) h1s[r][j] = fmaxf(s + s_b1[j], 0.f);
            }
        }
    }
    __syncthreads();

    // ---- phase 3: fc2 (32 x 32), all 256 threads active (R*H2 == 256) ----
    {
        int r = tid >> 5, j = tid & 31;
        float s = s_b2[j];
        #pragma unroll
        for (int k = 0; k < H2; ++k)
            s += h1s[r][k] * s_w2[j * 33 + k];
        h2s[r][j] = fmaxf(s, 0.f);
    }
    __syncthreads();

    // ---- phase 4: fc3 (1 x 32) ----
    if (tid < R) {
        float s = s_b3;
        #pragma unroll
        for (int k = 0; k < H3; ++k)
            s += h2s[tid][k] * s_w3[k];
        out[row0 + tid] = s;
    }
}

extern "C" void kernel_launch(void* const* d_in, const int* in_sizes, int n_in,
                              void* d_out, int out_size) {
    // metadata order:
    // 0 white_indices, 1 white_offsets (unused), 2 black_indices,
    // 3 black_offsets (unused), 4 ft_white, 5 ft_black,
    // 6 fc1_w, 7 fc1_b, 8 fc2_w, 9 fc2_b, 10 fc3_w, 11 fc3_b
    const void*  wi  = d_in[0];
    const void*  bi  = d_in[2];
    const float* ftw = (const float*)d_in[4];
    const float* ftb = (const float*)d_in[5];
    const float* w1  = (const float*)d_in[6];
    const float* b1  = (const float*)d_in[7];
    const float* w2  = (const float*)d_in[8];
    const float* b2  = (const float*)d_in[9];
    const float* w3  = (const float*)d_in[10];
    const float* b3  = (const float*)d_in[11];

    nnue_kernel<<<BATCH / R, THREADS>>>(wi, bi, ftw, ftb,
                                        w1, b1, w2, b2, w3, b3,
                                        (float*)d_out);
}

// round 6
// speedup vs baseline: 1.1977x; 1.0649x over previous
#include <cuda_runtime.h>
#include <cuda_fp16.h>

#define NUM_EMB 41025
#define BATCH   16384
#define BAG     30
#define H1      256
#define H2      32
#define H3      32
#define R       8          // batch rows per block
#define THREADS 256

#define TBL_ELEMS (NUM_EMB * H1)            // 10,502,400 halves per table
#define TBL_VEC4  (TBL_ELEMS / 8)           // uint4 (8 halves) per table

// Legal scratch: static __device__ arrays (21 MB per table, fp16)
__device__ uint4 g_ft16[2][TBL_VEC4];

// ---- per-launch fp32 -> fp16 table conversion (DRAM-bound, ~18us) ----
// one float4 (4 floats) -> one uint2 (4 halves) per thread
__global__ __launch_bounds__(512) void convert_tables(
    const float4* __restrict__ ftw, const float4* __restrict__ ftb)
{
    const int total = 2 * (TBL_ELEMS / 4);
    int i = blockIdx.x * 512 + threadIdx.x;
    if (i >= total) return;
    int t = (i >= TBL_ELEMS / 4);
    int j = t ? i - TBL_ELEMS / 4 : i;
    float4 v = __ldcs(t ? ftb + j : ftw + j);   // streaming: don't pollute L2
    half2 h0 = __floats2half2_rn(v.x, v.y);
    half2 h1 = __floats2half2_rn(v.z, v.w);
    uint2 o;
    o.x = *(unsigned*)&h0;
    o.y = *(unsigned*)&h1;
    ((uint2*)g_ft16[t])[j] = o;
}

__global__ __launch_bounds__(THREADS, 4) void nnue_kernel(
    const void* __restrict__ wi_raw, const void* __restrict__ bi_raw,
    const float* __restrict__ w1,  const float* __restrict__ b1,
    const float* __restrict__ w2,  const float* __restrict__ b2,
    const float* __restrict__ w3,  const float* __restrict__ b3,
    float* __restrict__ out)
{
    __shared__ int   s_idx[2][R][BAG];
    __shared__ float xs[R][2 * H1];          // 16 KB: concat(relu(w), relu(b)) per row
    __shared__ float h1s[R][H2];
    __shared__ float h2s[R][H3];
    __shared__ float s_w2[H2 * 33];          // padded stride 33 -> conflict-free
    __shared__ float s_b1[H2], s_b2[H2], s_w3[H3];
    __shared__ float s_b3;
    __shared__ int   s_is64;

    const int tid  = threadIdx.x;
    const int row0 = blockIdx.x * R;

    // ---- inline int32-vs-int64 index dtype detection ----
    if (tid < 16) {
        unsigned v = ((const unsigned*)wi_raw)[2 * tid + 1];
        unsigned nz = __ballot_sync(0xffffu, v != 0u);
        if (tid == 0) s_is64 = (nz == 0u);
    }
    __syncthreads();
    const int is64 = s_is64;

    // ---- load indices for this block's R rows (both colors) ----
    for (int t = tid; t < 2 * R * BAG; t += THREADS) {   // 480 indices
        int h   = t / (R * BAG);
        int rem = t % (R * BAG);
        int r   = rem / BAG, i = rem % BAG;
        const void* src = h ? bi_raw : wi_raw;
        long long pos = (long long)(row0 + r) * BAG + i;
        int idx;
        if (is64) idx = (int)((const long long*)src)[pos];
        else      idx = ((const int*)src)[pos];
        s_idx[h][r][i] = idx;
    }
    // ---- stage small weights into shared ----
    for (int j = tid; j < H2 * H2; j += THREADS) {
        int jr = j / H2, jc = j % H2;
        s_w2[jr * 33 + jc] = w2[j];
    }
    if      (tid < H2)            s_b1[tid] = b1[tid];
    else if (tid < 2 * H2)        s_b2[tid - H2] = b2[tid - H2];
    else if (tid < 2 * H2 + H3)   s_w3[tid - 2 * H2] = w3[tid - 2 * H2];
    else if (tid == 2 * H2 + H3)  s_b3 = b3[0];
    __syncthreads();

    // ---- phase 1: fp16 embedding-bag gathers (L2-BW-bound hot loop) ----
    // One warp covers a full 512B fp16 row (uint4 = 8 halves per lane).
    // 8 warps: warp w -> color h = w>>2, handles rows {w&3, (w&3)+4}.
    {
        const int warp = tid >> 5, lane = tid & 31;
        const int h    = warp >> 2;
        const int wr   = warp & 3;
        const uint4* tbl = g_ft16[h];
        #pragma unroll
        for (int rr = 0; rr < 2; ++rr) {
            const int r = wr + rr * 4;
            float a0 = 0.f, a1 = 0.f, a2 = 0.f, a3 = 0.f;
            float a4 = 0.f, a5 = 0.f, a6 = 0.f, a7 = 0.f;
            #pragma unroll
            for (int i = 0; i < BAG; ++i) {
                int idx = s_idx[h][r][i];
                uint4 v = __ldcg(tbl + idx * (H1 / 8) + lane);
                float2 f0 = __half22float2(*(half2*)&v.x);
                float2 f1 = __half22float2(*(half2*)&v.y);
                float2 f2 = __half22float2(*(half2*)&v.z);
                float2 f3 = __half22float2(*(half2*)&v.w);
                a0 += f0.x; a1 += f0.y; a2 += f1.x; a3 += f1.y;
                a4 += f2.x; a5 += f2.y; a6 += f3.x; a7 += f3.y;
            }
            float* dst = &xs[r][h * H1 + lane * 8];
            dst[0] = fmaxf(a0, 0.f); dst[1] = fmaxf(a1, 0.f);
            dst[2] = fmaxf(a2, 0.f); dst[3] = fmaxf(a3, 0.f);
            dst[4] = fmaxf(a4, 0.f); dst[5] = fmaxf(a5, 0.f);
            dst[6] = fmaxf(a6, 0.f); dst[7] = fmaxf(a7, 0.f);
        }
    }
    __syncthreads();

    // ---- phase 2: fc1 (32 x 512), W1 in registers, reused across R rows ----
    {
        const int warp = tid >> 5, lane = tid & 31;
        #pragma unroll 1
        for (int jj = 0; jj < 4; ++jj) {
            int j = warp * 4 + jj;           // 8 warps x 4 = 32 outputs
            float w1r[16];
            #pragma unroll
            for (int m = 0; m < 16; ++m)
                w1r[m] = w1[j * 512 + lane + 32 * m];   // coalesced, L1-hot
            #pragma unroll
            for (int r = 0; r < R; ++r) {
                float s = 0.f;
                #pragma unroll
                for (int m = 0; m < 16; ++m)
                    s += w1r[m] * xs[r][lane + 32 * m];
                #pragma unroll
                for (int o = 16; o > 0; o >>= 1)
                    s += __shfl_xor_sync(0xffffffffu, s, o);
                if (lane == 0) h1s[r][j] = fmaxf(s + s_b1[j], 0.f);
            }
        }
    }
    __syncthreads();

    // ---- phase 3: fc2 (32 x 32), all 256 threads active (R*H2 == 256) ----
    {
        int r = tid >> 5, j = tid & 31;
        float s = s_b2[j];
        #pragma unroll
        for (int k = 0; k < H2; ++k)
            s += h1s[r][k] * s_w2[j * 33 + k];
        h2s[r][j] = fmaxf(s, 0.f);
    }
    __syncthreads();

    // ---- phase 4: fc3 (1 x 32) ----
    if (tid < R) {
        float s = s_b3;
        #pragma unroll
        for (int k = 0; k < H3; ++k)
            s += h2s[tid][k] * s_w3[k];
        out[row0 + tid] = s;
    }
}

extern "C" void kernel_launch(void* const* d_in, const int* in_sizes, int n_in,
                              void* d_out, int out_size) {
    // metadata order:
    // 0 white_indices, 1 white_offsets (unused), 2 black_indices,
    // 3 black_offsets (unused), 4 ft_white, 5 ft_black,
    // 6 fc1_w, 7 fc1_b, 8 fc2_w, 9 fc2_b, 10 fc3_w, 11 fc3_b
    const void*  wi  = d_in[0];
    const void*  bi  = d_in[2];
    const float* ftw = (const float*)d_in[4];
    const float* ftb = (const float*)d_in[5];
    const float* w1  = (const float*)d_in[6];
    const float* b1  = (const float*)d_in[7];
    const float* w2  = (const float*)d_in[8];
    const float* b2  = (const float*)d_in[9];
    const float* w3  = (const float*)d_in[10];
    const float* b3  = (const float*)d_in[11];

    const int conv_total  = 2 * (TBL_ELEMS / 4);
    const int conv_blocks = (conv_total + 511) / 512;
    convert_tables<<<conv_blocks, 512>>>((const float4*)ftw, (const float4*)ftb);
    nnue_kernel<<<BATCH / R, THREADS>>>(wi, bi,
                                        w1, b1, w2, b2, w3, b3,
                                        (float*)d_out);
}

// round 7
// speedup vs baseline: 1.2034x; 1.0048x over previous
#include <cuda_runtime.h>
#include <cuda_fp16.h>

#define NUM_EMB 41025
#define BATCH   16384
#define BAG     30
#define H1      256
#define H2      32
#define H3      32
#define R       8          // batch rows per block
#define THREADS 256

#define TBL_ELEMS (NUM_EMB * H1)            // 10,502,400 halves per table
#define TBL_VEC4  (TBL_ELEMS / 8)           // uint4 (8 halves) per table

// Legal scratch: static __device__ arrays (21 MB per table, fp16)
__device__ uint4 g_ft16[2][TBL_VEC4];

// ---- per-launch fp32 -> fp16 table conversion (DRAM-bound, ~15us) ----
__global__ __launch_bounds__(512) void convert_tables(
    const float4* __restrict__ ftw, const float4* __restrict__ ftb)
{
    const int total = 2 * (TBL_ELEMS / 4);
    int i = blockIdx.x * 512 + threadIdx.x;
    if (i >= total) return;
    int t = (i >= TBL_ELEMS / 4);
    int j = t ? i - TBL_ELEMS / 4 : i;
    float4 v = __ldcs(t ? ftb + j : ftw + j);   // streaming: don't pollute L2
    half2 h0 = __floats2half2_rn(v.x, v.y);
    half2 h1 = __floats2half2_rn(v.z, v.w);
    uint2 o;
    o.x = *(unsigned*)&h0;
    o.y = *(unsigned*)&h1;
    ((uint2*)g_ft16[t])[j] = o;
}

__global__ __launch_bounds__(THREADS, 4) void nnue_kernel(
    const void* __restrict__ wi_raw, const void* __restrict__ bi_raw,
    const float* __restrict__ w1,  const float* __restrict__ b1,
    const float* __restrict__ w2,  const float* __restrict__ b2,
    const float* __restrict__ w3,  const float* __restrict__ b3,
    float* __restrict__ out)
{
    __shared__ int   s_idx[2][R][BAG];
    __shared__ float xs[R][2 * H1];          // 16 KB: concat(relu(w), relu(b)) per row
    __shared__ float h1s[R][H2];
    __shared__ float h2s[R][H3];
    __shared__ float s_w2[H2 * 33];          // padded stride 33 -> conflict-free
    __shared__ float s_b1[H2], s_b2[H2], s_w3[H3];
    __shared__ float s_b3;
    __shared__ int   s_is64;

    const int tid  = threadIdx.x;
    const int row0 = blockIdx.x * R;

    // ---- inline int32-vs-int64 index dtype detection ----
    if (tid < 16) {
        unsigned v = ((const unsigned*)wi_raw)[2 * tid + 1];
        unsigned nz = __ballot_sync(0xffffu, v != 0u);
        if (tid == 0) s_is64 = (nz == 0u);
    }
    __syncthreads();
    const int is64 = s_is64;

    // ---- load indices for this block's R rows (both colors) ----
    for (int t = tid; t < 2 * R * BAG; t += THREADS) {   // 480 indices
        int h   = t / (R * BAG);
        int rem = t % (R * BAG);
        int r   = rem / BAG, i = rem % BAG;
        const void* src = h ? bi_raw : wi_raw;
        long long pos = (long long)(row0 + r) * BAG + i;
        int idx;
        if (is64) idx = (int)((const long long*)src)[pos];
        else      idx = ((const int*)src)[pos];
        s_idx[h][r][i] = idx;
    }
    // ---- stage small weights into shared ----
    for (int j = tid; j < H2 * H2; j += THREADS) {
        int jr = j / H2, jc = j % H2;
        s_w2[jr * 33 + jc] = w2[j];
    }
    if      (tid < H2)            s_b1[tid] = b1[tid];
    else if (tid < 2 * H2)        s_b2[tid - H2] = b2[tid - H2];
    else if (tid < 2 * H2 + H3)   s_w3[tid - 2 * H2] = w3[tid - 2 * H2];
    else if (tid == 2 * H2 + H3)  s_b3 = b3[0];
    __syncthreads();

    // ---- phase 1: fp16 gathers with pairwise HADD2 pre-reduction ----
    // One warp covers a full 512B fp16 row (uint4 = 8 halves per lane).
    // BAG=30 processed as 15 pairs: fp16 add of the pair, then fp32 accumulate.
    {
        const int warp = tid >> 5, lane = tid & 31;
        const int h    = warp >> 2;
        const int wr   = warp & 3;
        const uint4* tbl = g_ft16[h];
        #pragma unroll
        for (int rr = 0; rr < 2; ++rr) {
            const int r = wr + rr * 4;
            float a0 = 0.f, a1 = 0.f, a2 = 0.f, a3 = 0.f;
            float a4 = 0.f, a5 = 0.f, a6 = 0.f, a7 = 0.f;
            const int2* idxp = (const int2*)s_idx[h][r];
            #pragma unroll
            for (int p = 0; p < BAG / 2; ++p) {
                int2 ij = idxp[p];
                uint4 u = __ldcg(tbl + ij.x * (H1 / 8) + lane);
                uint4 v = __ldcg(tbl + ij.y * (H1 / 8) + lane);
                half2 p0 = __hadd2(*(half2*)&u.x, *(half2*)&v.x);
                half2 p1 = __hadd2(*(half2*)&u.y, *(half2*)&v.y);
                half2 p2 = __hadd2(*(half2*)&u.z, *(half2*)&v.z);
                half2 p3 = __hadd2(*(half2*)&u.w, *(half2*)&v.w);
                float2 f0 = __half22float2(p0);
                float2 f1 = __half22float2(p1);
                float2 f2 = __half22float2(p2);
                float2 f3 = __half22float2(p3);
                a0 += f0.x; a1 += f0.y; a2 += f1.x; a3 += f1.y;
                a4 += f2.x; a5 += f2.y; a6 += f3.x; a7 += f3.y;
            }
            // two STS.128 (16 wavefronts vs 64 for conflicted scalars)
            float4* dst = (float4*)&xs[r][h * H1 + lane * 8];
            dst[0] = make_float4(fmaxf(a0, 0.f), fmaxf(a1, 0.f),
                                 fmaxf(a2, 0.f), fmaxf(a3, 0.f));
            dst[1] = make_float4(fmaxf(a4, 0.f), fmaxf(a5, 0.f),
                                 fmaxf(a6, 0.f), fmaxf(a7, 0.f));
        }
    }
    __syncthreads();

    // ---- phase 2: fc1 (32 x 512), 2-output blocking + float4 LDS ----
    // Each warp owns 4 outputs, processed as 2 passes of 2; every xs load is
    // reused for both outputs -> fc1 LDS traffic halved vs 1-output version.
    {
        const int warp = tid >> 5, lane = tid & 31;
        #pragma unroll 1
        for (int pass = 0; pass < 2; ++pass) {
            const int j0 = warp * 4 + pass * 2;
            float4 wa[4], wb[4];
            const float4* w1a = (const float4*)(w1 + j0 * 512);
            const float4* w1b = (const float4*)(w1 + (j0 + 1) * 512);
            #pragma unroll
            for (int m = 0; m < 4; ++m) {
                wa[m] = w1a[lane + 32 * m];     // coalesced, L1-hot
                wb[m] = w1b[lane + 32 * m];
            }
            #pragma unroll
            for (int r = 0; r < R; ++r) {
                const float4* xr = (const float4*)xs[r];
                float s0 = 0.f, s1 = 0.f;
                #pragma unroll
                for (int m = 0; m < 4; ++m) {
                    float4 x = xr[lane + 32 * m];
                    s0 += wa[m].x * x.x + wa[m].y * x.y
                        + wa[m].z * x.z + wa[m].w * x.w;
                    s1 += wb[m].x * x.x + wb[m].y * x.y
                        + wb[m].z * x.z + wb[m].w * x.w;
                }
                #pragma unroll
                for (int o = 16; o > 0; o >>= 1) {
                    s0 += __shfl_xor_sync(0xffffffffu, s0, o);
                    s1 += __shfl_xor_sync(0xffffffffu, s1, o);
                }
                if (lane == 0) {
                    h1s[r][j0]     = fmaxf(s0 + s_b1[j0],     0.f);
                    h1s[r][j0 + 1] = fmaxf(s1 + s_b1[j0 + 1], 0.f);
                }
            }
        }
    }
    __syncthreads();

    // ---- phase 3: fc2 (32 x 32), all 256 threads active (R*H2 == 256) ----
    {
        int r = tid >> 5, j = tid & 31;
        float s = s_b2[j];
        #pragma unroll
        for (int k = 0; k < H2; ++k)
            s += h1s[r][k] * s_w2[j * 33 + k];
        h2s[r][j] = fmaxf(s, 0.f);
    }
    __syncthreads();

    // ---- phase 4: fc3 (1 x 32) ----
    if (tid < R) {
        float s = s_b3;
        #pragma unroll
        for (int k = 0; k < H3; ++k)
            s += h2s[tid][k] * s_w3[k];
        out[row0 + tid] = s;
    }
}

extern "C" void kernel_launch(void* const* d_in, const int* in_sizes, int n_in,
                              void* d_out, int out_size) {
    // metadata order:
    // 0 white_indices, 1 white_offsets (unused), 2 black_indices,
    // 3 black_offsets (unused), 4 ft_white, 5 ft_black,
    // 6 fc1_w, 7 fc1_b, 8 fc2_w, 9 fc2_b, 10 fc3_w, 11 fc3_b
    const void*  wi  = d_in[0];
    const void*  bi  = d_in[2];
    const float* ftw = (const float*)d_in[4];
    const float* ftb = (const float*)d_in[5];
    const float* w1  = (const float*)d_in[6];
    const float* b1  = (const float*)d_in[7];
    const float* w2  = (const float*)d_in[8];
    const float* b2  = (const float*)d_in[9];
    const float* w3  = (const float*)d_in[10];
    const float* b3  = (const float*)d_in[11];

    const int conv_total  = 2 * (TBL_ELEMS / 4);
    const int conv_blocks = (conv_total + 511) / 512;
    convert_tables<<<conv_blocks, 512>>>((const float4*)ftw, (const float4*)ftb);
    nnue_kernel<<<BATCH / R, THREADS>>>(wi, bi,
                                        w1, b1, w2, b2, w3, b3,
                                        (float*)d_out);
}

// round 8
// speedup vs baseline: 1.2233x; 1.0166x over previous
#include <cuda_runtime.h>
#include <cuda_fp16.h>

#define NUM_EMB 41025
#define BATCH   16384
#define BAG     30
#define H1      256
#define H2      32
#define H3      32
#define R       8          // batch rows per block
#define THREADS 256

#define TBL_ELEMS (NUM_EMB * H1)            // 10,502,400 halves per table
#define TBL_VEC4  (TBL_ELEMS / 8)           // uint4 (8 halves) per table

typedef unsigned long long u64;

// Packed f32x2 FMA (sm_103a FFMA2 — only reachable via PTX fma.rn.f32x2)
#define FMA_F32X2(acc, a, b) \
    asm("fma.rn.f32x2 %0, %1, %2, %0;" : "+l"(acc) : "l"(a), "l"(b))
#define ADD_F32X2(acc, a) \
    asm("add.rn.f32x2 %0, %0, %1;" : "+l"(acc) : "l"(a))

__device__ __forceinline__ float f32x2_hsum(u64 v) {
    return __uint_as_float((unsigned)v) + __uint_as_float((unsigned)(v >> 32));
}

// Legal scratch: static __device__ arrays (21 MB per table, fp16)
__device__ uint4 g_ft16[2][TBL_VEC4];

// ---- per-launch fp32 -> fp16 table conversion (DRAM-bound, ~15us) ----
__global__ __launch_bounds__(512) void convert_tables(
    const float4* __restrict__ ftw, const float4* __restrict__ ftb)
{
    const int total = 2 * (TBL_ELEMS / 4);
    int i = blockIdx.x * 512 + threadIdx.x;
    if (i >= total) return;
    int t = (i >= TBL_ELEMS / 4);
    int j = t ? i - TBL_ELEMS / 4 : i;
    float4 v = __ldcs(t ? ftb + j : ftw + j);   // streaming read: don't pollute L2
    half2 h0 = __floats2half2_rn(v.x, v.y);
    half2 h1 = __floats2half2_rn(v.z, v.w);
    uint2 o;
    o.x = *(unsigned*)&h0;
    o.y = *(unsigned*)&h1;
    ((uint2*)g_ft16[t])[j] = o;                 // default store: warms L2 with fp16 table
}

__global__ __launch_bounds__(THREADS, 4) void nnue_kernel(
    const void* __restrict__ wi_raw, const void* __restrict__ bi_raw,
    const float* __restrict__ w1,  const float* __restrict__ b1,
    const float* __restrict__ w2,  const float* __restrict__ b2,
    const float* __restrict__ w3,  const float* __restrict__ b3,
    float* __restrict__ out)
{
    __shared__ __align__(16) int s_idx[2][R][32];   // padded to 32 for int4 reads
    __shared__ float xs[R][2 * H1];          // 16 KB: concat(relu(w), relu(b)) per row
    __shared__ float h1s[R][H2];
    __shared__ float h2s[R][H3];
    __shared__ float s_w2[H2 * 33];          // padded stride 33 -> conflict-free
    __shared__ float s_b1[H2], s_b2[H2], s_w3[H3];
    __shared__ float s_b3;
    __shared__ int   s_is64;

    const int tid  = threadIdx.x;
    const int row0 = blockIdx.x * R;

    // ---- inline int32-vs-int64 index dtype detection ----
    if (tid < 16) {
        unsigned v = ((const unsigned*)wi_raw)[2 * tid + 1];
        unsigned nz = __ballot_sync(0xffffu, v != 0u);
        if (tid == 0) s_is64 = (nz == 0u);
    }
    __syncthreads();
    const int is64 = s_is64;

    // ---- load indices for this block's R rows (both colors) ----
    for (int t = tid; t < 2 * R * BAG; t += THREADS) {   // 480 indices
        int h   = t / (R * BAG);
        int rem = t % (R * BAG);
        int r   = rem / BAG, i = rem % BAG;
        const void* src = h ? bi_raw : wi_raw;
        long long pos = (long long)(row0 + r) * BAG + i;
        int idx;
        if (is64) idx = (int)((const long long*)src)[pos];
        else      idx = ((const int*)src)[pos];
        s_idx[h][r][i] = idx;
    }
    // ---- stage small weights into shared ----
    for (int j = tid; j < H2 * H2; j += THREADS) {
        int jr = j / H2, jc = j % H2;
        s_w2[jr * 33 + jc] = w2[j];
    }
    if      (tid < H2)            s_b1[tid] = b1[tid];
    else if (tid < 2 * H2)        s_b2[tid - H2] = b2[tid - H2];
    else if (tid < 2 * H2 + H3)   s_w3[tid - 2 * H2] = w3[tid - 2 * H2];
    else if (tid == 2 * H2 + H3)  s_b3 = b3[0];
    __syncthreads();

    // ---- phase 1: fp16 gathers, 4-way HADD2 reduction tree ----
    // One warp covers a full 512B fp16 row (uint4 = 8 halves per lane).
    // BAG=30 = 7 groups of 4 (2-level fp16 tree) + 1 pair (1-level).
    {
        const int warp = tid >> 5, lane = tid & 31;
        const int h    = warp >> 2;
        const int wr   = warp & 3;
        const uint4* tbl = g_ft16[h];
        #pragma unroll
        for (int rr = 0; rr < 2; ++rr) {
            const int r = wr + rr * 4;
            float a0 = 0.f, a1 = 0.f, a2 = 0.f, a3 = 0.f;
            float a4 = 0.f, a5 = 0.f, a6 = 0.f, a7 = 0.f;
            const int4* idxq = (const int4*)s_idx[h][r];
            #pragma unroll
            for (int g = 0; g < 7; ++g) {
                int4 ij = idxq[g];
                uint4 u0 = __ldcg(tbl + ij.x * (H1 / 8) + lane);
                uint4 u1 = __ldcg(tbl + ij.y * (H1 / 8) + lane);
                uint4 u2 = __ldcg(tbl + ij.z * (H1 / 8) + lane);
                uint4 u3 = __ldcg(tbl + ij.w * (H1 / 8) + lane);
                half2 t0 = __hadd2(__hadd2(*(half2*)&u0.x, *(half2*)&u1.x),
                                   __hadd2(*(half2*)&u2.x, *(half2*)&u3.x));
                half2 t1 = __hadd2(__hadd2(*(half2*)&u0.y, *(half2*)&u1.y),
                                   __hadd2(*(half2*)&u2.y, *(half2*)&u3.y));
                half2 t2 = __hadd2(__hadd2(*(half2*)&u0.z, *(half2*)&u1.z),
                                   __hadd2(*(half2*)&u2.z, *(half2*)&u3.z));
                half2 t3 = __hadd2(__hadd2(*(half2*)&u0.w, *(half2*)&u1.w),
                                   __hadd2(*(half2*)&u2.w, *(half2*)&u3.w));
                float2 f0 = __half22float2(t0);
                float2 f1 = __half22float2(t1);
                float2 f2 = __half22float2(t2);
                float2 f3 = __half22float2(t3);
                a0 += f0.x; a1 += f0.y; a2 += f1.x; a3 += f1.y;
                a4 += f2.x; a5 += f2.y; a6 += f3.x; a7 += f3.y;
            }
            {   // tail pair: items 28, 29
                int2 ij = ((const int2*)s_idx[h][r])[14];
                uint4 u = __ldcg(tbl + ij.x * (H1 / 8) + lane);
                uint4 v = __ldcg(tbl + ij.y * (H1 / 8) + lane);
                float2 f0 = __half22float2(__hadd2(*(half2*)&u.x, *(half2*)&v.x));
                float2 f1 = __half22float2(__hadd2(*(half2*)&u.y, *(half2*)&v.y));
                float2 f2 = __half22float2(__hadd2(*(half2*)&u.z, *(half2*)&v.z));
                float2 f3 = __half22float2(__hadd2(*(half2*)&u.w, *(half2*)&v.w));
                a0 += f0.x; a1 += f0.y; a2 += f1.x; a3 += f1.y;
                a4 += f2.x; a5 += f2.y; a6 += f3.x; a7 += f3.y;
            }
            float4* dst = (float4*)&xs[r][h * H1 + lane * 8];
            dst[0] = make_float4(fmaxf(a0, 0.f), fmaxf(a1, 0.f),
                                 fmaxf(a2, 0.f), fmaxf(a3, 0.f));
            dst[1] = make_float4(fmaxf(a4, 0.f), fmaxf(a5, 0.f),
                                 fmaxf(a6, 0.f), fmaxf(a7, 0.f));
        }
    }
    __syncthreads();

    // ---- phase 2: fc1 (32 x 512) with packed f32x2 FMA ----
    // Weights and xs read as double2 (LDS.128 -> two f32x2 payloads).
    // Each warp: 4 outputs in 2 passes of 2; fused dual-output reduction.
    {
        const int warp = tid >> 5, lane = tid & 31;
        #pragma unroll 1
        for (int pass = 0; pass < 2; ++pass) {
            const int j0 = warp * 4 + pass * 2;
            double2 wa[4], wb[4];
            const double2* w1a = (const double2*)(w1 + j0 * 512);
            const double2* w1b = (const double2*)(w1 + (j0 + 1) * 512);
            #pragma unroll
            for (int m = 0; m < 4; ++m) {
                wa[m] = w1a[lane + 32 * m];     // coalesced, L1-hot
                wb[m] = w1b[lane + 32 * m];
            }
            #pragma unroll
            for (int r = 0; r < R; ++r) {
                const double2* xr = (const double2*)xs[r];
                u64 acc0a = 0ull, acc0b = 0ull, acc1a = 0ull, acc1b = 0ull;
                #pragma unroll
                for (int m = 0; m < 4; ++m) {
                    double2 x = xr[lane + 32 * m];
                    u64 xlo = __double_as_longlong(x.x);
                    u64 xhi = __double_as_longlong(x.y);
                    FMA_F32X2(acc0a, __double_as_longlong(wa[m].x), xlo);
                    FMA_F32X2(acc0b, __double_as_longlong(wa[m].y), xhi);
                    FMA_F32X2(acc1a, __double_as_longlong(wb[m].x), xlo);
                    FMA_F32X2(acc1b, __double_as_longlong(wb[m].y), xhi);
                }
                ADD_F32X2(acc0a, acc0b);
                ADD_F32X2(acc1a, acc1b);
                float s0 = f32x2_hsum(acc0a);
                float s1 = f32x2_hsum(acc1a);
                // fused dual reduction: fold s0 (lanes<16) / s1 (lanes>=16)
                float o0 = __shfl_xor_sync(0xffffffffu, s0, 16);
                float o1 = __shfl_xor_sync(0xffffffffu, s1, 16);
                float s  = (lane < 16) ? (s0 + o0) : (s1 + o1);
                #pragma unroll
                for (int o = 8; o > 0; o >>= 1)
                    s += __shfl_xor_sync(0xffffffffu, s, o);
                if (lane == 0)  h1s[r][j0]     = fmaxf(s + s_b1[j0],     0.f);
                if (lane == 16) h1s[r][j0 + 1] = fmaxf(s + s_b1[j0 + 1], 0.f);
            }
        }
    }
    __syncthreads();

    // ---- phase 3: fc2 (32 x 32), all 256 threads active (R*H2 == 256) ----
    {
        int r = tid >> 5, j = tid & 31;
        float s = s_b2[j];
        #pragma unroll
        for (int k = 0; k < H2; ++k)
            s += h1s[r][k] * s_w2[j * 33 + k];
        h2s[r][j] = fmaxf(s, 0.f);
    }
    __syncthreads();

    // ---- phase 4: fc3 (1 x 32) ----
    if (tid < R) {
        float s = s_b3;
        #pragma unroll
        for (int k = 0; k < H3; ++k)
            s += h2s[tid][k] * s_w3[k];
        out[row0 + tid] = s;
    }
}

extern "C" void kernel_launch(void* const* d_in, const int* in_sizes, int n_in,
                              void* d_out, int out_size) {
    // metadata order:
    // 0 white_indices, 1 white_offsets (unused), 2 black_indices,
    // 3 black_offsets (unused), 4 ft_white, 5 ft_black,
    // 6 fc1_w, 7 fc1_b, 8 fc2_w, 9 fc2_b, 10 fc3_w, 11 fc3_b
    const void*  wi  = d_in[0];
    const void*  bi  = d_in[2];
    const float* ftw = (const float*)d_in[4];
    const float* ftb = (const float*)d_in[5];
    const float* w1  = (const float*)d_in[6];
    const float* b1  = (const float*)d_in[7];
    const float* w2  = (const float*)d_in[8];
    const float* b2  = (const float*)d_in[9];
    const float* w3  = (const float*)d_in[10];
    const float* b3  = (const float*)d_in[11];

    const int conv_total  = 2 * (TBL_ELEMS / 4);
    const int conv_blocks = (conv_total + 511) / 512;
    convert_tables<<<conv_blocks, 512>>>((const float4*)ftw, (const float4*)ftb);
    nnue_kernel<<<BATCH / R, THREADS>>>(wi, bi,
                                        w1, b1, w2, b2, w3, b3,
                                        (float*)d_out);
}